// round 16
// baseline (speedup 1.0000x reference)
#include <cuda_runtime.h>
#include <cuda_fp16.h>
#include <cuda_bf16.h>
#include <cstdint>

// ---------------------------------------------------------------------------
// Problem constants
// ---------------------------------------------------------------------------
#define BATCH   4
#define SEQ     4096
#define DMODEL  1024
#define NHEADS  8
#define HDIM    64
#define STATE   512            // NHEADS*HDIM
#define PROJW   2048           // 4*STATE
#define ROWS    (BATCH*SEQ)    // 16384

// GEMM tiling: block 128x256, 8 warps of 64x64, fp16 HMMA m16n8k16
#define BM 128
#define BN 256
#define NSTAGE 5
#define ROWB 48                         // padded smem row stride (bytes)
#define A_STAGE_B (BM * ROWB)           // 6144 B
#define B_STAGE_B (BN * ROWB)           // 12288 B
#define GEMM_SMEM_BYTES (NSTAGE * (A_STAGE_B + B_STAGE_B))   // 92160 B

#define NTILES_N 8                      // 2048 / BN
#define NMTILES  128                    // ROWS / BM
#define NCVT     128                    // convert blocks

// Scan input staging: chunks of 64 steps, 3 operands (xi_raw | xf | xr)
#define CHUNK    64
#define NCHUNKS  (SEQ / CHUNK)          // 64
#define OP_STRIDE  (CHUNK * 64)         // 4096 floats per operand
#define BUF_STRIDE (3 * OP_STRIDE)      // 12288 floats per buffer
#define SCAN_SMEM_BYTES (2 * BUF_STRIDE * 4)   // 98304 B

#define SMEM_DYN_BYTES (SCAN_SMEM_BYTES > GEMM_SMEM_BYTES ? \
                        SCAN_SMEM_BYTES : GEMM_SMEM_BYTES)   // 98304

// Fused grid layout: scan | convert | gemm1-split | gemm1 | epilogue | gemm2
#define BLK_CVT0    32
#define BLK_G1S     (BLK_CVT0 + NCVT)                 // 160
#define BLK_G1N     (BLK_G1S + 4 * NTILES_N * 2)      // 224
#define BLK_EPI     (BLK_G1N + (NMTILES - 4) * NTILES_N)  // 1216
#define BLK_GEMM2   (BLK_EPI + NMTILES)               // 1344
#define BLK_TOTAL   (BLK_GEMM2 + NMTILES * 4)         // 1856

// Flag buffer layout
#define F_PROJ   0        // [0,128)   proj m-tile done (target 8, or 16 split)
#define F_Y      128      // [128,256) y m-tile done (target 8)
#define F_YN     256      // [256,384) ynh m-tile done (target 1)
#define F_WCVT   384      // w_in converted (target NCVT)
#define F_WOCVT  385      // w_out converted (target NCVT)
#define F_XCVT   386      // [386,514) x m-tile converted (target 1)
#define F_TOTAL  514

#define PROJ_TARGET(by) (((by) & 31) == 0 ? 2 * NTILES_N : NTILES_N)

// ---------------------------------------------------------------------------
// Scratch (device globals -- no runtime allocation allowed)
// ---------------------------------------------------------------------------
__device__ float  g_proj[(size_t)ROWS * PROJW];   // [xi_raw | xf | xr | g]
__device__ float  g_y   [(size_t)ROWS * STATE];   // recurrence output
__device__ __half g_xh  [(size_t)ROWS * DMODEL];  // x (fp16)
__device__ __half g_winh[(size_t)PROJW * DMODEL]; // w_in (fp16; xf/xr rows *0.5)
__device__ __half g_wouth[(size_t)DMODEL * STATE];// w_out (fp16)
__device__ __half g_ynh [(size_t)ROWS * STATE];   // gated+normed (fp16)
__device__ int    g_flagbuf[F_TOTAL];             // zeroed via cudaMemsetAsync

// ---------------------------------------------------------------------------
// Helpers
// ---------------------------------------------------------------------------
__device__ __forceinline__ unsigned long long pk2(float lo, float hi) {
    unsigned long long r;
    asm("mov.b64 %0, {%1, %2};" : "=l"(r) : "f"(lo), "f"(hi));
    return r;
}
__device__ __forceinline__ void fma2(unsigned long long& d,
                                     unsigned long long a,
                                     unsigned long long b) {
    asm("fma.rn.f32x2 %0, %1, %2, %0;" : "+l"(d) : "l"(a), "l"(b));
}
__device__ __forceinline__ unsigned long long add2(unsigned long long a,
                                                   unsigned long long b) {
    unsigned long long d;
    asm("add.rn.f32x2 %0, %1, %2;" : "=l"(d) : "l"(a), "l"(b));
    return d;
}
__device__ __forceinline__ float hadd2(unsigned long long v) {
    float a, b;
    asm("mov.b64 {%0, %1}, %2;" : "=f"(a), "=f"(b) : "l"(v));
    return a + b;
}
__device__ __forceinline__ float fsigmoid(float x) {
    return __fdividef(1.0f, 1.0f + __expf(-x));
}
__device__ __forceinline__ float tanh_fast(float x) {
    float y;
    asm("tanh.approx.f32 %0, %1;" : "=f"(y) : "f"(x));
    return y;
}
__device__ __forceinline__ float sigmoid_fast(float x) {
    return fmaf(0.5f, tanh_fast(0.5f * x), 0.5f);
}
// argument already pre-halved (weights prescaled by 0.5)
__device__ __forceinline__ float sigmoid_pre(float half_arg) {
    return fmaf(0.5f, tanh_fast(half_arg), 0.5f);
}
__device__ __forceinline__ int ld_acq(const int* p) {
    int v;
    asm volatile("ld.global.acquire.gpu.b32 %0, [%1];" : "=r"(v) : "l"(p));
    return v;
}
__device__ __forceinline__ void wait_flag(const int* p, int target) {
    while (ld_acq(p) < target) { __nanosleep(128); }
}
__device__ __forceinline__ float4 ldcg4(const float* p) {
    float4 v;
    asm volatile("ld.global.cg.v4.f32 {%0,%1,%2,%3}, [%4];"
                 : "=f"(v.x), "=f"(v.y), "=f"(v.z), "=f"(v.w) : "l"(p));
    return v;
}
// convert 8 floats -> 8 halves with scale
__device__ __forceinline__ void cvt8(const float* src, __half* dst, float s) {
    const float4* sp = (const float4*)src;
    float4 a = sp[0], b = sp[1];
    __half2 h0 = __floats2half2_rn(a.x * s, a.y * s);
    __half2 h1 = __floats2half2_rn(a.z * s, a.w * s);
    __half2 h2 = __floats2half2_rn(b.x * s, b.y * s);
    __half2 h3 = __floats2half2_rn(b.z * s, b.w * s);
    uint4 o;
    o.x = *(uint32_t*)&h0; o.y = *(uint32_t*)&h1;
    o.z = *(uint32_t*)&h2; o.w = *(uint32_t*)&h3;
    *(uint4*)dst = o;
}

// ---------------------------------------------------------------------------
// GEMM primitives
// ---------------------------------------------------------------------------
__device__ __forceinline__ void mma_f16(float* c, const uint32_t* a,
                                        uint32_t b0, uint32_t b1) {
    asm volatile(
        "mma.sync.aligned.m16n8k16.row.col.f32.f16.f16.f32 "
        "{%0,%1,%2,%3}, {%4,%5,%6,%7}, {%8,%9}, {%0,%1,%2,%3};\n"
        : "+f"(c[0]), "+f"(c[1]), "+f"(c[2]), "+f"(c[3])
        : "r"(a[0]), "r"(a[1]), "r"(a[2]), "r"(a[3]), "r"(b0), "r"(b1));
}
__device__ __forceinline__ void ldsm4(uint32_t& r0, uint32_t& r1,
                                      uint32_t& r2, uint32_t& r3,
                                      uint32_t addr) {
    asm volatile("ldmatrix.sync.aligned.m8n8.x4.shared.b16 "
                 "{%0,%1,%2,%3}, [%4];"
                 : "=r"(r0), "=r"(r1), "=r"(r2), "=r"(r3) : "r"(addr));
}
__device__ __forceinline__ void cp16(uint32_t dst, const void* src) {
    asm volatile("cp.async.cg.shared.global [%0], [%1], 16;\n"
                 :: "r"(dst), "l"(src));
}

// ---------------------------------------------------------------------------
// Convert body: block j converts its w_in slice, its x m-tile, its w_out
// slice; publishes flags after each. No waits -> always runs to completion.
// ---------------------------------------------------------------------------
__device__ void convert_body(const float* __restrict__ x, __half* xh,
                             const float* __restrict__ w_in, __half* winh,
                             const float* __restrict__ w_out, __half* wouth,
                             int j)
{
    const int tid = threadIdx.x;

    // 1) w_in slice: 2048 groups of 8 (prescale xf|xr rows by 0.5, exact)
    {
        const int base = j * 2048;
#pragma unroll
        for (int i = 0; i < 8; i++) {
            const int g = base + i * 256 + tid;
            const int row = g >> 7;                 // 128 groups per row
            const float s = (row >= 512 && row < 1536) ? 0.5f : 1.0f;
            cvt8(w_in + (size_t)g * 8, winh + (size_t)g * 8, s);
        }
        __threadfence();
        __syncthreads();
        if (tid == 0) atomicAdd(&g_flagbuf[F_WCVT], 1);
    }
    // 2) x m-tile (time-first order): 16384 groups
    {
        const int by = (j & 3) * 32 + (j >> 2);
        const size_t gbase = (size_t)by * BM * (DMODEL / 8);
#pragma unroll 8
        for (int i = 0; i < 64; i++) {
            const size_t g = gbase + i * 256 + tid;
            cvt8(x + g * 8, xh + g * 8, 1.0f);
        }
        __threadfence();
        __syncthreads();
        if (tid == 0) atomicAdd(&g_flagbuf[F_XCVT + by], 1);
    }
    // 3) w_out slice: 512 groups
    {
        const int base = j * 512;
#pragma unroll
        for (int i = 0; i < 2; i++) {
            const int g = base + i * 256 + tid;
            cvt8(w_out + (size_t)g * 8, wouth + (size_t)g * 8, 1.0f);
        }
        __threadfence();
        __syncthreads();
        if (tid == 0) atomicAdd(&g_flagbuf[F_WOCVT], 1);
    }
}

// ---------------------------------------------------------------------------
// 128x256 fp16 GEMM body (NT): C[m,n] = sum_k A[m,k]*B[n,k], fp32 accum.
// Kiter = summed K, stride = row stride of A and B. accum -> atomicAdd store.
// ---------------------------------------------------------------------------
__device__ __forceinline__ void gemm_body(const __half* __restrict__ Ag0,
                                          const __half* __restrict__ Bg0,
                                          float* __restrict__ Cg0,
                                          int Kiter, int stride, int ldc,
                                          bool accum)
{
    extern __shared__ char smem_dyn[];
    char* Asm = smem_dyn;
    char* Bsm = smem_dyn + NSTAGE * A_STAGE_B;
    const uint32_t aBase = (uint32_t)__cvta_generic_to_shared(Asm);
    const uint32_t bBase = (uint32_t)__cvta_generic_to_shared(Bsm);

    const int tid   = threadIdx.x;
    const int lane  = tid & 31;
    const int warp  = tid >> 5;
    const int group = lane >> 2;
    const int tig   = lane & 3;
    const int wm = (warp >> 2) * 64;
    const int wn = (warp & 3) * 64;

    const int lj = lane >> 3;
    const int lrr = lane & 7;
    const uint32_t fragOff =
        (uint32_t)(((lj & 1) * 8 + lrr) * ROWB + (lj >> 1) * 16);

    float c[4][8][4];
#pragma unroll
    for (int mt = 0; mt < 4; mt++)
#pragma unroll
        for (int nt = 0; nt < 8; nt++)
#pragma unroll
            for (int q = 0; q < 4; q++) c[mt][nt][q] = 0.0f;

    const int arow  = tid >> 1;
    const int ahalf = tid & 1;
    const uint32_t aOff  = (uint32_t)(arow * ROWB + ahalf * 16);
    const uint32_t bOff0 = aOff;
    const uint32_t bOff1 = (uint32_t)((arow + 128) * ROWB + ahalf * 16);
    const int niter = Kiter >> 4;

    auto load_stage = [&](int st, int ko) {
        const uint32_t aS = aBase + (uint32_t)(st * A_STAGE_B);
        const uint32_t bS = bBase + (uint32_t)(st * B_STAGE_B);
        cp16(aS + aOff,  Ag0 + (size_t)arow * stride + ko + ahalf * 8);
        cp16(bS + bOff0, Bg0 + (size_t)arow * stride + ko + ahalf * 8);
        cp16(bS + bOff1, Bg0 + (size_t)(arow + 128) * stride + ko + ahalf * 8);
        asm volatile("cp.async.commit_group;\n");
    };

    load_stage(0, 0);
    load_stage(1, 16);
    load_stage(2, 32);
    load_stage(3, 48);

    int st = 0, ldst = 4;
    for (int it = 0; it < niter; it++) {
        asm volatile("cp.async.wait_group 3;\n");
        __syncthreads();

        const uint32_t aT = aBase + (uint32_t)(st * A_STAGE_B);
        const uint32_t bT = bBase + (uint32_t)(st * B_STAGE_B);

        uint32_t a[4][4], bf[4][4];
#pragma unroll
        for (int mt = 0; mt < 4; mt++)
            ldsm4(a[mt][0], a[mt][1], a[mt][2], a[mt][3],
                  aT + (uint32_t)((wm + mt * 16) * ROWB) + fragOff);
#pragma unroll
        for (int bt = 0; bt < 4; bt++)
            ldsm4(bf[bt][0], bf[bt][1], bf[bt][2], bf[bt][3],
                  bT + (uint32_t)((wn + bt * 16) * ROWB) + fragOff);

#pragma unroll
        for (int mt = 0; mt < 4; mt++)
#pragma unroll
            for (int nt = 0; nt < 8; nt++) {
                const int bt = nt >> 1, s = nt & 1;
                mma_f16(c[mt][nt], a[mt], bf[bt][s], bf[bt][s + 2]);
            }

        if (it + 4 < niter)
            load_stage(ldst, (it + 4) * 16);
        else
            asm volatile("cp.async.commit_group;\n");

        st   = (st   + 1 == NSTAGE) ? 0 : st + 1;
        ldst = (ldst + 1 == NSTAGE) ? 0 : ldst + 1;
    }

#pragma unroll
    for (int mt = 0; mt < 4; mt++) {
        const int m0 = wm + mt * 16 + group;
#pragma unroll
        for (int nt = 0; nt < 8; nt++) {
            const int n0 = wn + nt * 8 + 2 * tig;
            float* p0 = Cg0 + (size_t)m0 * ldc + n0;
            float* p1 = Cg0 + (size_t)(m0 + 8) * ldc + n0;
            if (accum) {
                atomicAdd(p0,     c[mt][nt][0]);
                atomicAdd(p0 + 1, c[mt][nt][1]);
                atomicAdd(p1,     c[mt][nt][2]);
                atomicAdd(p1 + 1, c[mt][nt][3]);
            } else {
                *(float2*)p0 = make_float2(c[mt][nt][0], c[mt][nt][1]);
                *(float2*)p1 = make_float2(c[mt][nt][2], c[mt][nt][3]);
            }
        }
    }
}

// ---------------------------------------------------------------------------
// Sequential recurrence (R15 step structure); y store moved to r-threads.
// ---------------------------------------------------------------------------
__device__ void scan_body(const float* proj,
                          const float* __restrict__ cw,
                          const float* __restrict__ sw,
                          float* __restrict__ y, int bh, float* stage)
{
    const int tid  = threadIdx.x;
    const int k    = tid & 63;
    const bool isf = tid < 64;
    const int head = bh & 7;
    const int b    = bh >> 3;

    int* flags_proj = g_flagbuf + F_PROJ;
    int* flags_y    = g_flagbuf + F_Y;

    __shared__ __align__(16) float h_sh[64];
    __shared__ __align__(16) float hr_sh[64];
    __shared__ __align__(16) float xi_sh[2][64];   // conv+silu handoff

    unsigned long long wg[32];  // 0.5*Wf (f) or 0.5*Wr (r), column k
    unsigned long long wz[32];  // W  (f-threads only)
    {
        const int gidx = isf ? (NHEADS + head) : (2 * NHEADS + head);
        const float* base = sw + (size_t)gidx * 64 * 64 + k;
#pragma unroll
        for (int i = 0; i < 32; i++)
            wg[i] = pk2(0.5f * base[(2 * i) * 64],
                        0.5f * base[(2 * i + 1) * 64]);
        if (isf) {
            const float* bz = sw + (size_t)head * 64 * 64 + k;
#pragma unroll
            for (int i = 0; i < 32; i++)
                wz[i] = pk2(bz[(2 * i) * 64], bz[(2 * i + 1) * 64]);
        }
    }

    // conv weights + rolling window: r-threads only
    float cw0 = 0.f, cw1 = 0.f, cw2 = 0.f, cw3 = 0.f;
    if (!isf) {
        const float* cwp = cw + (size_t)(head * HDIM + k) * 4;
        cw0 = cwp[0]; cw1 = cwp[1]; cw2 = cwp[2]; cw3 = cwp[3];
    }
    float rm1 = 0.f, rm2 = 0.f, rm3 = 0.f;
    float h_reg = 0.f;                  // f's own h[k]

    if (tid < 64) h_sh[tid] = 0.0f;

    const size_t rowbase = (size_t)b * SEQ;

    const int trow = tid >> 4;      // 0..7
    const int tq4  = tid & 15;      // 0..15
    const uint32_t stBase = (uint32_t)__cvta_generic_to_shared(stage);

    auto stage_chunk = [&](int ch) {
        const int s0 = ch * CHUNK;
        const uint32_t dst0 = stBase
            + (uint32_t)((ch & 1) * BUF_STRIDE) * 4u;
        const float* src0 = proj + (rowbase + s0) * PROJW
                            + head * HDIM + tq4 * 4;
#pragma unroll
        for (int op = 0; op < 3; op++) {
            const int opoff = op * STATE;
#pragma unroll
            for (int i = 0; i < 8; i++) {
                const int row = i * 8 + trow;
                cp16(dst0 + (uint32_t)((op * OP_STRIDE + row * 64 + tq4 * 4) * 4),
                     src0 + (size_t)row * PROJW + opoff);
            }
        }
    };

    // tile 0 of this batch is a K-split tile: target 16
    if (tid == 0) wait_flag(&flags_proj[b * 32 + 0], PROJ_TARGET(b * 32));
    __syncthreads();
    stage_chunk(0); asm volatile("cp.async.commit_group;\n");
    stage_chunk(1); asm volatile("cp.async.commit_group;\n");

    float* y_ptr = y + rowbase * STATE + head * HDIM + k;

    const ulonglong2* hp  = (const ulonglong2*)h_sh;
    const ulonglong2* hrp = (const ulonglong2*)hr_sh;

    for (int ch = 0; ch < NCHUNKS; ch++) {
        asm volatile("cp.async.wait_group 1;\n");
        __syncthreads();

        const float* bufp = stage + (ch & 1) * BUF_STRIDE;
        const float* xg_s = bufp + (isf ? OP_STRIDE : 2 * OP_STRIDE) + k;
        const float* xi_raw_s = bufp + k;     // op 0: raw xi
        const int sb = ch * CHUNK;

        // chunk top: r computes conv+silu for step 0
        if (!isf) {
            const float raw = xi_raw_s[0];
            const float a = fmaf(cw3, raw,
                             fmaf(cw2, rm1, fmaf(cw1, rm2, cw0 * rm3)));
            xi_sh[0][k] = a * sigmoid_fast(a);
            rm3 = rm2; rm2 = rm1; rm1 = raw;
        }

#pragma unroll 8
        for (int js = 0; js < CHUNK; js++) {
            const float xg = xg_s[js * 64];   // pre-halved (prescaled w_in)

            // phase A: gate dot over h; xg folded into accumulator init
            unsigned long long a0 = pk2(xg, 0.0f);
            unsigned long long a1 = 0ull, a2 = 0ull, a3 = 0ull;
#pragma unroll
            for (int i = 0; i < 8; i++) {
                ulonglong2 p0 = hp[2 * i];
                ulonglong2 p1 = hp[2 * i + 1];
                fma2(a0, p0.x, wg[4 * i + 0]);
                fma2(a1, p0.y, wg[4 * i + 1]);
                fma2(a2, p1.x, wg[4 * i + 2]);
                fma2(a3, p1.y, wg[4 * i + 3]);
            }
            const float gate =
                sigmoid_pre(hadd2(add2(add2(a0, a1), add2(a2, a3))));
            if (!isf) hr_sh[k] = h_sh[k] * gate;
            __syncthreads();                       // bar1: hr (+xi) visible

            if (isf) {
                // pre-compute the post-tanh algebra off the serial chain
                const float p = gate * h_reg;      // g*h
                const float q = 1.0f - gate;       // (1-g)
                const float xiv = xi_sh[js & 1][k];
                unsigned long long z0 = pk2(xiv, 0.0f);
                unsigned long long z1 = 0ull, z2 = 0ull, z3 = 0ull;
#pragma unroll
                for (int i = 0; i < 8; i++) {
                    ulonglong2 p0 = hrp[2 * i];
                    ulonglong2 p1 = hrp[2 * i + 1];
                    fma2(z0, p0.x, wz[4 * i + 0]);
                    fma2(z1, p0.y, wz[4 * i + 1]);
                    fma2(z2, p1.x, wz[4 * i + 2]);
                    fma2(z3, p1.y, wz[4 * i + 3]);
                }
                const float z =
                    tanh_fast(hadd2(add2(add2(z0, z1), add2(z2, z3))));
                const float hn = fmaf(q, z, p);    // g*h + (1-g)*z
                h_sh[k] = hn;
                h_reg = hn;
            } else if (js < CHUNK - 1) {
                // phase B (r): conv+silu for step js+1 into the other slot
                const float raw = xi_raw_s[(js + 1) * 64];
                const float a = fmaf(cw3, raw,
                                 fmaf(cw2, rm1, fmaf(cw1, rm2, cw0 * rm3)));
                xi_sh[(js + 1) & 1][k] = a * sigmoid_fast(a);
                rm3 = rm2; rm2 = rm1; rm1 = raw;
            }
            __syncthreads();                       // bar2: new h visible

            // r stores y (off f's critical path); safe: f rewrites h_sh[k]
            // only after the NEXT bar1.
            if (!isf) y_ptr[(size_t)(sb + js) * STATE] = h_sh[k];
        }

        // publish y progress for the m-tile just completed (every 2 chunks)
        if (ch & 1) {
            __threadfence();
            __syncthreads();
            if (tid == 0) atomicAdd(&flags_y[b * 32 + (ch >> 1)], 1);
        }

        if (ch + 2 < NCHUNKS) {
            if (tid == 0) wait_flag(&flags_proj[b * 32 + ((ch + 2) >> 1)],
                                    NTILES_N);   // tiles t>=1 are non-split
            __syncthreads();
            stage_chunk(ch + 2);
        }
        asm volatile("cp.async.commit_group;\n");
    }
}

// ---------------------------------------------------------------------------
// Epilogue body: one m-tile (128 rows). Gated on y + g availability.
// ---------------------------------------------------------------------------
__device__ void epilogue_body(const float* y, const float* proj,
                              const float* __restrict__ norm_w,
                              __half* yn, int by)
{
    const int tid = threadIdx.x;
    if (tid == 0) {
        wait_flag(&g_flagbuf[F_PROJ + by], PROJ_TARGET(by));  // g cols ready
        wait_flag(&g_flagbuf[F_Y + by], NHEADS);              // y rows ready
    }
    __syncthreads();

    const int w = tid >> 5, lane = tid & 31;
    float nw[16];
#pragma unroll
    for (int j = 0; j < 4; j++) {
        float4 t = *(const float4*)(norm_w + lane * 4 + j * 128);
        nw[4 * j + 0] = t.x; nw[4 * j + 1] = t.y;
        nw[4 * j + 2] = t.z; nw[4 * j + 3] = t.w;
    }

    for (int rr = 0; rr < 16; rr++) {
        const int row = by * BM + w * 16 + rr;
        const float* yr = y    + (size_t)row * STATE;
        const float* gr = proj + (size_t)row * PROJW + 3 * STATE;
        float v[16];
        float ss = 0.0f;
#pragma unroll
        for (int j = 0; j < 4; j++) {
            float4 yv = ldcg4(yr + lane * 4 + j * 128);
            float4 gv = ldcg4(gr + lane * 4 + j * 128);
            float v0 = yv.x * gv.x * fsigmoid(gv.x);
            float v1 = yv.y * gv.y * fsigmoid(gv.y);
            float v2 = yv.z * gv.z * fsigmoid(gv.z);
            float v3 = yv.w * gv.w * fsigmoid(gv.w);
            v[4 * j + 0] = v0; v[4 * j + 1] = v1;
            v[4 * j + 2] = v2; v[4 * j + 3] = v3;
            ss += v0 * v0 + v1 * v1 + v2 * v2 + v3 * v3;
        }
#pragma unroll
        for (int off = 16; off > 0; off >>= 1)
            ss += __shfl_xor_sync(0xffffffffu, ss, off);
        const float scale = rsqrtf(ss * (1.0f / 512.0f) + 1e-6f);
        __half* outr = yn + (size_t)row * STATE;
#pragma unroll
        for (int j = 0; j < 4; j++) {
            __half2 h0 = __floats2half2_rn(v[4 * j + 0] * scale * nw[4 * j + 0],
                                           v[4 * j + 1] * scale * nw[4 * j + 1]);
            __half2 h1 = __floats2half2_rn(v[4 * j + 2] * scale * nw[4 * j + 2],
                                           v[4 * j + 3] * scale * nw[4 * j + 3]);
            uint2 o;
            o.x = *(uint32_t*)&h0; o.y = *(uint32_t*)&h1;
            *(uint2*)(outr + lane * 4 + j * 128) = o;
        }
    }

    __threadfence();
    __syncthreads();
    if (tid == 0) atomicAdd(&g_flagbuf[F_YN + by], 1);
}

// ---------------------------------------------------------------------------
// Fused kernel: scan | convert | gemm1-split | gemm1 | epilogue | gemm2
// All dependencies flow strictly forward in block index -> deadlock-free.
// ---------------------------------------------------------------------------
__global__ void __launch_bounds__(256)
fused_all(float* proj,
          const float* __restrict__ cw,
          const float* __restrict__ sw,
          float* __restrict__ y,
          const float* __restrict__ x, __half* xh,
          const float* __restrict__ w_in, __half* winh,
          const float* __restrict__ w_out, __half* wouth,
          const float* __restrict__ norm_w,
          __half* ynh,
          float* __restrict__ out)
{
    extern __shared__ char smem_dyn[];
    const int bx = blockIdx.x;
    if (bx < BLK_CVT0) {
        if (threadIdx.x >= 128) return;
        scan_body(proj, cw, sw, y, bx, (float*)smem_dyn);
    } else if (bx < BLK_G1S) {
        convert_body(x, xh, w_in, winh, w_out, wouth, bx - BLK_CVT0);
    } else if (bx < BLK_G1N) {
        // K-split first tiles: by in {0,32,64,96}, 2 K-halves, atomic accum
        const int idx  = bx - BLK_G1S;
        const int half = idx & 1;
        const int nt   = (idx >> 1) & 7;
        const int by   = (idx >> 4) * 32;
        if (threadIdx.x == 0) {
            wait_flag(&g_flagbuf[F_WCVT], NCVT);
            wait_flag(&g_flagbuf[F_XCVT + by], 1);
        }
        __syncthreads();
        gemm_body(xh + (size_t)by * BM * DMODEL + half * 512,
                  winh + (size_t)nt * BN * DMODEL + half * 512,
                  proj + (size_t)by * BM * PROJW + nt * BN,
                  512, DMODEL, PROJW, true);
        __threadfence();
        __syncthreads();
        if (threadIdx.x == 0) atomicAdd(&g_flagbuf[F_PROJ + by], 1);
    } else if (bx < BLK_EPI) {
        const int idx = bx - BLK_G1N;
        const int nt = idx & 7;
        const int m_order = 4 + (idx >> 3);       // 4..127, time-first
        const int by = (m_order & 3) * 32 + (m_order >> 2);
        if (threadIdx.x == 0) {
            wait_flag(&g_flagbuf[F_WCVT], NCVT);
            wait_flag(&g_flagbuf[F_XCVT + by], 1);
        }
        __syncthreads();
        gemm_body(xh + (size_t)by * BM * DMODEL,
                  winh + (size_t)nt * BN * DMODEL,
                  proj + (size_t)by * BM * PROJW + nt * BN,
                  DMODEL, DMODEL, PROJW, false);
        __threadfence();
        __syncthreads();
        if (threadIdx.x == 0) atomicAdd(&g_flagbuf[F_PROJ + by], 1);
    } else if (bx < BLK_GEMM2) {
        const int m_order = bx - BLK_EPI;
        const int by = (m_order & 3) * 32 + (m_order >> 2);
        epilogue_body(y, proj, norm_w, ynh, by);
    } else {
        const int idx = bx - BLK_GEMM2;
        const int nt = idx & 3;
        const int m_order = idx >> 2;
        const int by = (m_order & 3) * 32 + (m_order >> 2);
        if (threadIdx.x == 0) {
            wait_flag(&g_flagbuf[F_WOCVT], NCVT);
            wait_flag(&g_flagbuf[F_YN + by], 1);
        }
        __syncthreads();
        gemm_body(ynh + (size_t)by * BM * STATE,
                  wouth + (size_t)nt * BN * STATE,
                  out + (size_t)by * BM * DMODEL + nt * BN,
                  STATE, STATE, DMODEL, false);
    }
}

// ---------------------------------------------------------------------------
// Launch
// ---------------------------------------------------------------------------
extern "C" void kernel_launch(void* const* d_in, const int* in_sizes, int n_in,
                              void* d_out, int out_size)
{
    const float* x      = (const float*)d_in[0];
    const float* w_in   = (const float*)d_in[1];
    const float* conv_w = (const float*)d_in[2];
    const float* sw     = (const float*)d_in[3];
    const float* norm_w = (const float*)d_in[4];
    const float* w_out  = (const float*)d_in[5];
    float* out = (float*)d_out;

    float *proj, *y;
    __half *xh, *winh, *wouth, *ynh;
    int* flagbuf;
    cudaGetSymbolAddress((void**)&proj,    g_proj);
    cudaGetSymbolAddress((void**)&y,       g_y);
    cudaGetSymbolAddress((void**)&xh,      g_xh);
    cudaGetSymbolAddress((void**)&winh,    g_winh);
    cudaGetSymbolAddress((void**)&wouth,   g_wouth);
    cudaGetSymbolAddress((void**)&ynh,     g_ynh);
    cudaGetSymbolAddress((void**)&flagbuf, g_flagbuf);

    cudaFuncSetAttribute(fused_all,
                         cudaFuncAttributeMaxDynamicSharedMemorySize,
                         SMEM_DYN_BYTES);

    // 0. zero flags + zero the 4 K-split proj m-tiles (atomic accumulation)
    cudaMemsetAsync(flagbuf, 0, F_TOTAL * sizeof(int));
    for (int t = 0; t < 4; t++)
        cudaMemsetAsync(proj + (size_t)(t * 32) * BM * PROJW, 0,
                        (size_t)BM * PROJW * sizeof(float));

    // 1. single fused pipeline:
    //    convert -> proj GEMM (first tiles K-split) -> scan(+conv)
    //    -> epilogue -> out GEMM
    fused_all<<<BLK_TOTAL, 256, SMEM_DYN_BYTES>>>(
        proj, conv_w, sw, y, x, xh, w_in, winh, w_out, wouth,
        norm_w, ynh, out);
}

// round 17
// speedup vs baseline: 1.0022x; 1.0022x over previous
#include <cuda_runtime.h>
#include <cuda_fp16.h>
#include <cuda_bf16.h>
#include <cstdint>

// ---------------------------------------------------------------------------
// Problem constants
// ---------------------------------------------------------------------------
#define BATCH   4
#define SEQ     4096
#define DMODEL  1024
#define NHEADS  8
#define HDIM    64
#define STATE   512            // NHEADS*HDIM
#define PROJW   2048           // 4*STATE
#define ROWS    (BATCH*SEQ)    // 16384

// GEMM tiling: block 128x256, 8 warps of 64x64, fp16 HMMA m16n8k16
#define BM 128
#define BN 256
#define NSTAGE 5
#define ROWB 48                         // padded smem row stride (bytes)
#define A_STAGE_B (BM * ROWB)           // 6144 B
#define B_STAGE_B (BN * ROWB)           // 12288 B
#define GEMM_SMEM_BYTES (NSTAGE * (A_STAGE_B + B_STAGE_B))   // 92160 B

#define NTILES_N 8                      // 2048 / BN
#define NMTILES  128                    // ROWS / BM

// Scan input staging: chunks of 64 steps, 3 operands (xi_raw | xf | xr)
#define CHUNK    64
#define NCHUNKS  (SEQ / CHUNK)          // 64
#define OP_STRIDE  (CHUNK * 64)         // 4096 floats per operand
#define BUF_STRIDE (3 * OP_STRIDE)      // 12288 floats per buffer
#define SCAN_SMEM_BYTES (2 * BUF_STRIDE * 4)   // 98304 B

#define SMEM_DYN_BYTES (SCAN_SMEM_BYTES > GEMM_SMEM_BYTES ? \
                        SCAN_SMEM_BYTES : GEMM_SMEM_BYTES)   // 98304

// Fused grid layout: scan | gemm1-split(first 4 tiles) | gemm1 | epi | gemm2
#define BLK_G1S     32
#define BLK_G1N     (BLK_G1S + 4 * NTILES_N * 2)           // 96
#define BLK_EPI     (BLK_G1N + (NMTILES - 4) * NTILES_N)   // 1088
#define BLK_GEMM2   (BLK_EPI + NMTILES)                    // 1216
#define BLK_TOTAL   (BLK_GEMM2 + NMTILES * 4)              // 1728

// Flag buffer layout
#define F_PROJ   0        // [0,128)   proj m-tile done (8, or 16 if split)
#define F_Y      128      // [128,256) y m-tile done (target 8)
#define F_YN     256      // [256,384) ynh m-tile done (target 1)
#define F_TOTAL  384

#define PROJ_TARGET(by) (((by) & 31) == 0 ? 2 * NTILES_N : NTILES_N)

// Merged conversion sizes (groups of 8 floats)
#define CVT_N1 (ROWS * DMODEL / 8)      // x      : 2097152
#define CVT_N2 (PROJW * DMODEL / 8)     // w_in   : 262144
#define CVT_N3 (DMODEL * STATE / 8)     // w_out  : 65536
#define CVT_TOTAL (CVT_N1 + CVT_N2 + CVT_N3)

// ---------------------------------------------------------------------------
// Scratch (device globals -- no runtime allocation allowed)
// ---------------------------------------------------------------------------
__device__ float  g_proj[(size_t)ROWS * PROJW];   // [xi_raw | xf | xr | g]
__device__ float  g_y   [(size_t)ROWS * STATE];   // recurrence output
__device__ __half g_xh  [(size_t)ROWS * DMODEL];  // x (fp16)
__device__ __half g_winh[(size_t)PROJW * DMODEL]; // w_in (fp16; xf/xr rows *0.5)
__device__ __half g_wouth[(size_t)DMODEL * STATE];// w_out (fp16)
__device__ __half g_ynh [(size_t)ROWS * STATE];   // gated+normed (fp16)
__device__ int    g_flagbuf[F_TOTAL];             // zeroed via cudaMemsetAsync

// ---------------------------------------------------------------------------
// Helpers
// ---------------------------------------------------------------------------
__device__ __forceinline__ unsigned long long pk2(float lo, float hi) {
    unsigned long long r;
    asm("mov.b64 %0, {%1, %2};" : "=l"(r) : "f"(lo), "f"(hi));
    return r;
}
__device__ __forceinline__ void fma2(unsigned long long& d,
                                     unsigned long long a,
                                     unsigned long long b) {
    asm("fma.rn.f32x2 %0, %1, %2, %0;" : "+l"(d) : "l"(a), "l"(b));
}
__device__ __forceinline__ unsigned long long add2(unsigned long long a,
                                                   unsigned long long b) {
    unsigned long long d;
    asm("add.rn.f32x2 %0, %1, %2;" : "=l"(d) : "l"(a), "l"(b));
    return d;
}
__device__ __forceinline__ float hadd2(unsigned long long v) {
    float a, b;
    asm("mov.b64 {%0, %1}, %2;" : "=f"(a), "=f"(b) : "l"(v));
    return a + b;
}
__device__ __forceinline__ float fsigmoid(float x) {
    return __fdividef(1.0f, 1.0f + __expf(-x));
}
__device__ __forceinline__ float tanh_fast(float x) {
    float y;
    asm("tanh.approx.f32 %0, %1;" : "=f"(y) : "f"(x));
    return y;
}
__device__ __forceinline__ float sigmoid_fast(float x) {
    return fmaf(0.5f, tanh_fast(0.5f * x), 0.5f);
}
// argument already pre-halved (weights prescaled by 0.5)
__device__ __forceinline__ float sigmoid_pre(float half_arg) {
    return fmaf(0.5f, tanh_fast(half_arg), 0.5f);
}
__device__ __forceinline__ int ld_acq(const int* p) {
    int v;
    asm volatile("ld.global.acquire.gpu.b32 %0, [%1];" : "=r"(v) : "l"(p));
    return v;
}
__device__ __forceinline__ void wait_flag(const int* p, int target) {
    while (ld_acq(p) < target) { __nanosleep(128); }
}
__device__ __forceinline__ float4 ldcg4(const float* p) {
    float4 v;
    asm volatile("ld.global.cg.v4.f32 {%0,%1,%2,%3}, [%4];"
                 : "=f"(v.x), "=f"(v.y), "=f"(v.z), "=f"(v.w) : "l"(p));
    return v;
}

// ---------------------------------------------------------------------------
// GEMM primitives
// ---------------------------------------------------------------------------
__device__ __forceinline__ void mma_f16(float* c, const uint32_t* a,
                                        uint32_t b0, uint32_t b1) {
    asm volatile(
        "mma.sync.aligned.m16n8k16.row.col.f32.f16.f16.f32 "
        "{%0,%1,%2,%3}, {%4,%5,%6,%7}, {%8,%9}, {%0,%1,%2,%3};\n"
        : "+f"(c[0]), "+f"(c[1]), "+f"(c[2]), "+f"(c[3])
        : "r"(a[0]), "r"(a[1]), "r"(a[2]), "r"(a[3]), "r"(b0), "r"(b1));
}
__device__ __forceinline__ void ldsm4(uint32_t& r0, uint32_t& r1,
                                      uint32_t& r2, uint32_t& r3,
                                      uint32_t addr) {
    asm volatile("ldmatrix.sync.aligned.m8n8.x4.shared.b16 "
                 "{%0,%1,%2,%3}, [%4];"
                 : "=r"(r0), "=r"(r1), "=r"(r2), "=r"(r3) : "r"(addr));
}
__device__ __forceinline__ void cp16(uint32_t dst, const void* src) {
    asm volatile("cp.async.cg.shared.global [%0], [%1], 16;\n"
                 :: "r"(dst), "l"(src));
}

// ---------------------------------------------------------------------------
// Merged pre-pass: fp32 -> fp16 (rn). w_in rows [512,1536) (xf|xr) are
// prescaled by 0.5 (exact) so the scan's sigmoid needs no inner 0.5 mul.
// ---------------------------------------------------------------------------
__global__ void __launch_bounds__(256)
convert_all_kernel(const float* __restrict__ x, __half* __restrict__ xh,
                   const float* __restrict__ w_in, __half* __restrict__ winh,
                   const float* __restrict__ w_out, __half* __restrict__ wouth)
{
    int g = blockIdx.x * 256 + threadIdx.x;
    const float* src;
    __half* dst;
    float scale = 1.0f;
    if (g < CVT_N1) {
        src = x + (size_t)g * 8;            dst = xh + (size_t)g * 8;
    } else if (g < CVT_N1 + CVT_N2) {
        int h8 = g - CVT_N1;
        int row = h8 >> 7;                  // 128 groups of 8 per 1024-col row
        if (row >= 512 && row < 1536) scale = 0.5f;
        src = w_in + (size_t)h8 * 8;        dst = winh + (size_t)h8 * 8;
    } else if (g < CVT_TOTAL) {
        int h8 = g - CVT_N1 - CVT_N2;
        src = w_out + (size_t)h8 * 8;       dst = wouth + (size_t)h8 * 8;
    } else {
        return;
    }
    const float4* s = (const float4*)src;
    float4 a = s[0], b = s[1];
    __half2 h0 = __floats2half2_rn(a.x * scale, a.y * scale);
    __half2 h1 = __floats2half2_rn(a.z * scale, a.w * scale);
    __half2 h2 = __floats2half2_rn(b.x * scale, b.y * scale);
    __half2 h3 = __floats2half2_rn(b.z * scale, b.w * scale);
    uint4 o;
    o.x = *(uint32_t*)&h0; o.y = *(uint32_t*)&h1;
    o.z = *(uint32_t*)&h2; o.w = *(uint32_t*)&h3;
    *(uint4*)dst = o;
}

// ---------------------------------------------------------------------------
// 128x256 fp16 GEMM body (NT): C[m,n] = sum_k A[m,k]*B[n,k], fp32 accum.
// Kiter = summed K extent, stride = row stride. accum -> atomicAdd store.
// ---------------------------------------------------------------------------
__device__ __forceinline__ void gemm_body(const __half* __restrict__ Ag0,
                                          const __half* __restrict__ Bg0,
                                          float* __restrict__ Cg0,
                                          int Kiter, int stride, int ldc,
                                          bool accum)
{
    extern __shared__ char smem_dyn[];
    char* Asm = smem_dyn;
    char* Bsm = smem_dyn + NSTAGE * A_STAGE_B;
    const uint32_t aBase = (uint32_t)__cvta_generic_to_shared(Asm);
    const uint32_t bBase = (uint32_t)__cvta_generic_to_shared(Bsm);

    const int tid   = threadIdx.x;
    const int lane  = tid & 31;
    const int warp  = tid >> 5;
    const int group = lane >> 2;
    const int tig   = lane & 3;
    const int wm = (warp >> 2) * 64;
    const int wn = (warp & 3) * 64;

    const int lj = lane >> 3;
    const int lrr = lane & 7;
    const uint32_t fragOff =
        (uint32_t)(((lj & 1) * 8 + lrr) * ROWB + (lj >> 1) * 16);

    float c[4][8][4];
#pragma unroll
    for (int mt = 0; mt < 4; mt++)
#pragma unroll
        for (int nt = 0; nt < 8; nt++)
#pragma unroll
            for (int q = 0; q < 4; q++) c[mt][nt][q] = 0.0f;

    const int arow  = tid >> 1;
    const int ahalf = tid & 1;
    const uint32_t aOff  = (uint32_t)(arow * ROWB + ahalf * 16);
    const uint32_t bOff0 = aOff;
    const uint32_t bOff1 = (uint32_t)((arow + 128) * ROWB + ahalf * 16);
    const int niter = Kiter >> 4;

    auto load_stage = [&](int st, int ko) {
        const uint32_t aS = aBase + (uint32_t)(st * A_STAGE_B);
        const uint32_t bS = bBase + (uint32_t)(st * B_STAGE_B);
        cp16(aS + aOff,  Ag0 + (size_t)arow * stride + ko + ahalf * 8);
        cp16(bS + bOff0, Bg0 + (size_t)arow * stride + ko + ahalf * 8);
        cp16(bS + bOff1, Bg0 + (size_t)(arow + 128) * stride + ko + ahalf * 8);
        asm volatile("cp.async.commit_group;\n");
    };

    load_stage(0, 0);
    load_stage(1, 16);
    load_stage(2, 32);
    load_stage(3, 48);

    int st = 0, ldst = 4;
    for (int it = 0; it < niter; it++) {
        asm volatile("cp.async.wait_group 3;\n");
        __syncthreads();

        const uint32_t aT = aBase + (uint32_t)(st * A_STAGE_B);
        const uint32_t bT = bBase + (uint32_t)(st * B_STAGE_B);

        uint32_t a[4][4], bf[4][4];
#pragma unroll
        for (int mt = 0; mt < 4; mt++)
            ldsm4(a[mt][0], a[mt][1], a[mt][2], a[mt][3],
                  aT + (uint32_t)((wm + mt * 16) * ROWB) + fragOff);
#pragma unroll
        for (int bt = 0; bt < 4; bt++)
            ldsm4(bf[bt][0], bf[bt][1], bf[bt][2], bf[bt][3],
                  bT + (uint32_t)((wn + bt * 16) * ROWB) + fragOff);

#pragma unroll
        for (int mt = 0; mt < 4; mt++)
#pragma unroll
            for (int nt = 0; nt < 8; nt++) {
                const int bt = nt >> 1, s = nt & 1;
                mma_f16(c[mt][nt], a[mt], bf[bt][s], bf[bt][s + 2]);
            }

        if (it + 4 < niter)
            load_stage(ldst, (it + 4) * 16);
        else
            asm volatile("cp.async.commit_group;\n");

        st   = (st   + 1 == NSTAGE) ? 0 : st + 1;
        ldst = (ldst + 1 == NSTAGE) ? 0 : ldst + 1;
    }

#pragma unroll
    for (int mt = 0; mt < 4; mt++) {
        const int m0 = wm + mt * 16 + group;
#pragma unroll
        for (int nt = 0; nt < 8; nt++) {
            const int n0 = wn + nt * 8 + 2 * tig;
            float* p0 = Cg0 + (size_t)m0 * ldc + n0;
            float* p1 = Cg0 + (size_t)(m0 + 8) * ldc + n0;
            if (accum) {
                atomicAdd(p0,     c[mt][nt][0]);
                atomicAdd(p0 + 1, c[mt][nt][1]);
                atomicAdd(p1,     c[mt][nt][2]);
                atomicAdd(p1 + 1, c[mt][nt][3]);
            } else {
                *(float2*)p0 = make_float2(c[mt][nt][0], c[mt][nt][1]);
                *(float2*)p1 = make_float2(c[mt][nt][2], c[mt][nt][3]);
            }
        }
    }
}

// ---------------------------------------------------------------------------
// Sequential recurrence (R15 step structure); y store on r-threads.
// ---------------------------------------------------------------------------
__device__ void scan_body(const float* proj,
                          const float* __restrict__ cw,
                          const float* __restrict__ sw,
                          float* __restrict__ y, int bh, float* stage)
{
    const int tid  = threadIdx.x;
    const int k    = tid & 63;
    const bool isf = tid < 64;
    const int head = bh & 7;
    const int b    = bh >> 3;

    int* flags_proj = g_flagbuf + F_PROJ;
    int* flags_y    = g_flagbuf + F_Y;

    __shared__ __align__(16) float h_sh[64];
    __shared__ __align__(16) float hr_sh[64];
    __shared__ __align__(16) float xi_sh[2][64];   // conv+silu handoff

    unsigned long long wg[32];  // 0.5*Wf (f) or 0.5*Wr (r), column k
    unsigned long long wz[32];  // W  (f-threads only)
    {
        const int gidx = isf ? (NHEADS + head) : (2 * NHEADS + head);
        const float* base = sw + (size_t)gidx * 64 * 64 + k;
#pragma unroll
        for (int i = 0; i < 32; i++)
            wg[i] = pk2(0.5f * base[(2 * i) * 64],
                        0.5f * base[(2 * i + 1) * 64]);
        if (isf) {
            const float* bz = sw + (size_t)head * 64 * 64 + k;
#pragma unroll
            for (int i = 0; i < 32; i++)
                wz[i] = pk2(bz[(2 * i) * 64], bz[(2 * i + 1) * 64]);
        }
    }

    // conv weights + rolling window: r-threads only
    float cw0 = 0.f, cw1 = 0.f, cw2 = 0.f, cw3 = 0.f;
    if (!isf) {
        const float* cwp = cw + (size_t)(head * HDIM + k) * 4;
        cw0 = cwp[0]; cw1 = cwp[1]; cw2 = cwp[2]; cw3 = cwp[3];
    }
    float rm1 = 0.f, rm2 = 0.f, rm3 = 0.f;
    float h_reg = 0.f;                  // f's own h[k]

    if (tid < 64) h_sh[tid] = 0.0f;

    const size_t rowbase = (size_t)b * SEQ;

    const int trow = tid >> 4;      // 0..7
    const int tq4  = tid & 15;      // 0..15
    const uint32_t stBase = (uint32_t)__cvta_generic_to_shared(stage);

    auto stage_chunk = [&](int ch) {
        const int s0 = ch * CHUNK;
        const uint32_t dst0 = stBase
            + (uint32_t)((ch & 1) * BUF_STRIDE) * 4u;
        const float* src0 = proj + (rowbase + s0) * PROJW
                            + head * HDIM + tq4 * 4;
#pragma unroll
        for (int op = 0; op < 3; op++) {
            const int opoff = op * STATE;
#pragma unroll
            for (int i = 0; i < 8; i++) {
                const int row = i * 8 + trow;
                cp16(dst0 + (uint32_t)((op * OP_STRIDE + row * 64 + tq4 * 4) * 4),
                     src0 + (size_t)row * PROJW + opoff);
            }
        }
    };

    // tile 0 of this batch is a K-split tile: target 16
    if (tid == 0) wait_flag(&flags_proj[b * 32 + 0], PROJ_TARGET(b * 32));
    __syncthreads();
    stage_chunk(0); asm volatile("cp.async.commit_group;\n");
    stage_chunk(1); asm volatile("cp.async.commit_group;\n");

    float* y_ptr = y + rowbase * STATE + head * HDIM + k;

    const ulonglong2* hp  = (const ulonglong2*)h_sh;
    const ulonglong2* hrp = (const ulonglong2*)hr_sh;

    for (int ch = 0; ch < NCHUNKS; ch++) {
        asm volatile("cp.async.wait_group 1;\n");
        __syncthreads();

        const float* bufp = stage + (ch & 1) * BUF_STRIDE;
        const float* xg_s = bufp + (isf ? OP_STRIDE : 2 * OP_STRIDE) + k;
        const float* xi_raw_s = bufp + k;     // op 0: raw xi
        const int sb = ch * CHUNK;

        // chunk top: r computes conv+silu for step 0
        if (!isf) {
            const float raw = xi_raw_s[0];
            const float a = fmaf(cw3, raw,
                             fmaf(cw2, rm1, fmaf(cw1, rm2, cw0 * rm3)));
            xi_sh[0][k] = a * sigmoid_fast(a);
            rm3 = rm2; rm2 = rm1; rm1 = raw;
        }

#pragma unroll 8
        for (int js = 0; js < CHUNK; js++) {
            const float xg = xg_s[js * 64];   // pre-halved (prescaled w_in)

            // phase A: gate dot over h; xg folded into accumulator init
            unsigned long long a0 = pk2(xg, 0.0f);
            unsigned long long a1 = 0ull, a2 = 0ull, a3 = 0ull;
#pragma unroll
            for (int i = 0; i < 8; i++) {
                ulonglong2 p0 = hp[2 * i];
                ulonglong2 p1 = hp[2 * i + 1];
                fma2(a0, p0.x, wg[4 * i + 0]);
                fma2(a1, p0.y, wg[4 * i + 1]);
                fma2(a2, p1.x, wg[4 * i + 2]);
                fma2(a3, p1.y, wg[4 * i + 3]);
            }
            const float gate =
                sigmoid_pre(hadd2(add2(add2(a0, a1), add2(a2, a3))));
            if (!isf) hr_sh[k] = h_sh[k] * gate;
            __syncthreads();                       // bar1: hr (+xi) visible

            if (isf) {
                // pre-compute the post-tanh algebra off the serial chain
                const float p = gate * h_reg;      // g*h
                const float q = 1.0f - gate;       // (1-g)
                const float xiv = xi_sh[js & 1][k];
                unsigned long long z0 = pk2(xiv, 0.0f);
                unsigned long long z1 = 0ull, z2 = 0ull, z3 = 0ull;
#pragma unroll
                for (int i = 0; i < 8; i++) {
                    ulonglong2 p0 = hrp[2 * i];
                    ulonglong2 p1 = hrp[2 * i + 1];
                    fma2(z0, p0.x, wz[4 * i + 0]);
                    fma2(z1, p0.y, wz[4 * i + 1]);
                    fma2(z2, p1.x, wz[4 * i + 2]);
                    fma2(z3, p1.y, wz[4 * i + 3]);
                }
                const float z =
                    tanh_fast(hadd2(add2(add2(z0, z1), add2(z2, z3))));
                const float hn = fmaf(q, z, p);    // g*h + (1-g)*z
                h_sh[k] = hn;
                h_reg = hn;
            } else if (js < CHUNK - 1) {
                // phase B (r): conv+silu for step js+1 into the other slot
                const float raw = xi_raw_s[(js + 1) * 64];
                const float a = fmaf(cw3, raw,
                                 fmaf(cw2, rm1, fmaf(cw1, rm2, cw0 * rm3)));
                xi_sh[(js + 1) & 1][k] = a * sigmoid_fast(a);
                rm3 = rm2; rm2 = rm1; rm1 = raw;
            }
            __syncthreads();                       // bar2: new h visible

            // r stores y (off f's critical path); safe: f rewrites h_sh[k]
            // only after the NEXT bar1.
            if (!isf) y_ptr[(size_t)(sb + js) * STATE] = h_sh[k];
        }

        // publish y progress for the m-tile just completed (every 2 chunks)
        if (ch & 1) {
            __threadfence();
            __syncthreads();
            if (tid == 0) atomicAdd(&flags_y[b * 32 + (ch >> 1)], 1);
        }

        if (ch + 2 < NCHUNKS) {
            if (tid == 0) wait_flag(&flags_proj[b * 32 + ((ch + 2) >> 1)],
                                    NTILES_N);   // tiles t>=1 are non-split
            __syncthreads();
            stage_chunk(ch + 2);
        }
        asm volatile("cp.async.commit_group;\n");
    }
}

// ---------------------------------------------------------------------------
// Epilogue body: one m-tile (128 rows). Gated on y + g availability.
// ---------------------------------------------------------------------------
__device__ void epilogue_body(const float* y, const float* proj,
                              const float* __restrict__ norm_w,
                              __half* yn, int by)
{
    const int tid = threadIdx.x;
    if (tid == 0) {
        wait_flag(&g_flagbuf[F_PROJ + by], PROJ_TARGET(by));  // g cols ready
        wait_flag(&g_flagbuf[F_Y + by], NHEADS);              // y rows ready
    }
    __syncthreads();

    const int w = tid >> 5, lane = tid & 31;
    float nw[16];
#pragma unroll
    for (int j = 0; j < 4; j++) {
        float4 t = *(const float4*)(norm_w + lane * 4 + j * 128);
        nw[4 * j + 0] = t.x; nw[4 * j + 1] = t.y;
        nw[4 * j + 2] = t.z; nw[4 * j + 3] = t.w;
    }

    for (int rr = 0; rr < 16; rr++) {
        const int row = by * BM + w * 16 + rr;
        const float* yr = y    + (size_t)row * STATE;
        const float* gr = proj + (size_t)row * PROJW + 3 * STATE;
        float v[16];
        float ss = 0.0f;
#pragma unroll
        for (int j = 0; j < 4; j++) {
            float4 yv = ldcg4(yr + lane * 4 + j * 128);
            float4 gv = ldcg4(gr + lane * 4 + j * 128);
            float v0 = yv.x * gv.x * fsigmoid(gv.x);
            float v1 = yv.y * gv.y * fsigmoid(gv.y);
            float v2 = yv.z * gv.z * fsigmoid(gv.z);
            float v3 = yv.w * gv.w * fsigmoid(gv.w);
            v[4 * j + 0] = v0; v[4 * j + 1] = v1;
            v[4 * j + 2] = v2; v[4 * j + 3] = v3;
            ss += v0 * v0 + v1 * v1 + v2 * v2 + v3 * v3;
        }
#pragma unroll
        for (int off = 16; off > 0; off >>= 1)
            ss += __shfl_xor_sync(0xffffffffu, ss, off);
        const float scale = rsqrtf(ss * (1.0f / 512.0f) + 1e-6f);
        __half* outr = yn + (size_t)row * STATE;
#pragma unroll
        for (int j = 0; j < 4; j++) {
            __half2 h0 = __floats2half2_rn(v[4 * j + 0] * scale * nw[4 * j + 0],
                                           v[4 * j + 1] * scale * nw[4 * j + 1]);
            __half2 h1 = __floats2half2_rn(v[4 * j + 2] * scale * nw[4 * j + 2],
                                           v[4 * j + 3] * scale * nw[4 * j + 3]);
            uint2 o;
            o.x = *(uint32_t*)&h0; o.y = *(uint32_t*)&h1;
            *(uint2*)(outr + lane * 4 + j * 128) = o;
        }
    }

    __threadfence();
    __syncthreads();
    if (tid == 0) atomicAdd(&g_flagbuf[F_YN + by], 1);
}

// ---------------------------------------------------------------------------
// Fused kernel: scan | gemm1-split | gemm1 | epilogue | gemm2.
// Split blocks (first-needed tiles) sit in wave 1 next to the scan.
// ---------------------------------------------------------------------------
__global__ void __launch_bounds__(256)
fused_all(float* proj,
          const float* __restrict__ cw,
          const float* __restrict__ sw,
          float* __restrict__ y,
          const __half* __restrict__ xh,
          const __half* __restrict__ winh,
          const float* __restrict__ norm_w,
          __half* ynh,
          const __half* __restrict__ wouth,
          float* __restrict__ out)
{
    extern __shared__ char smem_dyn[];
    const int bx = blockIdx.x;
    if (bx < BLK_G1S) {
        if (threadIdx.x >= 128) return;
        scan_body(proj, cw, sw, y, bx, (float*)smem_dyn);
    } else if (bx < BLK_G1N) {
        // K-split first tiles: by in {0,32,64,96}, 2 K-halves, atomic accum
        const int idx  = bx - BLK_G1S;
        const int half = idx & 1;
        const int nt   = (idx >> 1) & 7;
        const int by   = (idx >> 4) * 32;
        gemm_body(xh + (size_t)by * BM * DMODEL + half * 512,
                  winh + (size_t)nt * BN * DMODEL + half * 512,
                  proj + (size_t)by * BM * PROJW + nt * BN,
                  512, DMODEL, PROJW, true);
        __threadfence();
        __syncthreads();
        if (threadIdx.x == 0) atomicAdd(&g_flagbuf[F_PROJ + by], 1);
    } else if (bx < BLK_EPI) {
        const int idx = bx - BLK_G1N;
        const int nt = idx & 7;
        const int m_order = 4 + (idx >> 3);       // 4..127, time-first
        const int by = (m_order & 3) * 32 + (m_order >> 2);
        gemm_body(xh + (size_t)by * BM * DMODEL,
                  winh + (size_t)nt * BN * DMODEL,
                  proj + (size_t)by * BM * PROJW + nt * BN,
                  DMODEL, DMODEL, PROJW, false);
        __threadfence();
        __syncthreads();
        if (threadIdx.x == 0) atomicAdd(&g_flagbuf[F_PROJ + by], 1);
    } else if (bx < BLK_GEMM2) {
        const int m_order = bx - BLK_EPI;
        const int by = (m_order & 3) * 32 + (m_order >> 2);
        epilogue_body(y, proj, norm_w, ynh, by);
    } else {
        const int idx = bx - BLK_GEMM2;
        const int nt = idx & 3;
        const int m_order = idx >> 2;
        const int by = (m_order & 3) * 32 + (m_order >> 2);
        if (threadIdx.x == 0) wait_flag(&g_flagbuf[F_YN + by], 1);
        __syncthreads();
        gemm_body(ynh + (size_t)by * BM * STATE,
                  wouth + (size_t)nt * BN * STATE,
                  out + (size_t)by * BM * DMODEL + nt * BN,
                  STATE, STATE, DMODEL, false);
    }
}

// ---------------------------------------------------------------------------
// Launch
// ---------------------------------------------------------------------------
extern "C" void kernel_launch(void* const* d_in, const int* in_sizes, int n_in,
                              void* d_out, int out_size)
{
    const float* x      = (const float*)d_in[0];
    const float* w_in   = (const float*)d_in[1];
    const float* conv_w = (const float*)d_in[2];
    const float* sw     = (const float*)d_in[3];
    const float* norm_w = (const float*)d_in[4];
    const float* w_out  = (const float*)d_in[5];
    float* out = (float*)d_out;

    float *proj, *y;
    __half *xh, *winh, *wouth, *ynh;
    int* flagbuf;
    cudaGetSymbolAddress((void**)&proj,    g_proj);
    cudaGetSymbolAddress((void**)&y,       g_y);
    cudaGetSymbolAddress((void**)&xh,      g_xh);
    cudaGetSymbolAddress((void**)&winh,    g_winh);
    cudaGetSymbolAddress((void**)&wouth,   g_wouth);
    cudaGetSymbolAddress((void**)&ynh,     g_ynh);
    cudaGetSymbolAddress((void**)&flagbuf, g_flagbuf);

    cudaFuncSetAttribute(fused_all,
                         cudaFuncAttributeMaxDynamicSharedMemorySize,
                         SMEM_DYN_BYTES);

    // 0. zero flags + zero the 4 K-split proj m-tiles (atomic accumulation);
    //    overlapped with the conversion kernel.
    cudaMemsetAsync(flagbuf, 0, F_TOTAL * sizeof(int));
    for (int t = 0; t < 4; t++)
        cudaMemsetAsync(proj + (size_t)(t * 32) * BM * PROJW, 0,
                        (size_t)BM * PROJW * sizeof(float));
    convert_all_kernel<<<(CVT_TOTAL + 255) / 256, 256>>>(
        x, xh, w_in, winh, w_out, wouth);

    // 1. fused pipeline: proj GEMM (first tiles K-split, wave-1 resident)
    //    -> scan(+conv) -> epilogue -> out GEMM
    fused_all<<<BLK_TOTAL, 256, SMEM_DYN_BYTES>>>(
        proj, conv_w, sw, y, xh, winh, norm_w, ynh, wouth, out);
}